// round 8
// baseline (speedup 1.0000x reference)
#include <cuda_runtime.h>
#include <math.h>
#include <stdint.h>

#define D_IN   768
#define TWO_D  1536
#define Q_N    128
#define S_N    512
#define C_N    64
#define JCHUNKS 8
#define JPER   (TWO_D / JCHUNKS)    /* 192 */
#define KSPLIT 384                  /* K per split-K CTA */

typedef unsigned long long ull;

// Scratch (device globals: allocation-free per harness rules)
__device__ float    v8_hq0[Q_N * TWO_D];            // hq partial k[0,384) (+b1)
__device__ float    v8_hq1[Q_N * TWO_D];            // hq partial k[384,768)
__device__ float    v8_hs0[S_N * TWO_D];
__device__ float    v8_hs1[S_N * TWO_D];
__device__ double   v8_part[JCHUNKS * Q_N * S_N];   // fp64 partial scores per j-chunk
__device__ double   v8_loss[Q_N];
__device__ unsigned v8_ticket = 0;

// fp32 -> tf32 RNA rounding (matches cuBLAS TF32 input quantization = reference)
__device__ __forceinline__ float v8_tf32(float x) {
    unsigned u;
    asm("cvt.rna.tf32.f32 %0, %1;" : "=r"(u) : "f"(x));
    return __uint_as_float(u);
}

// m16n8k8 tf32 mma (base ISA, sm_80+)
__device__ __forceinline__ void v8_mma(float d[4], const unsigned a[4], const unsigned b[2]) {
    asm volatile(
        "mma.sync.aligned.m16n8k8.row.col.f32.tf32.tf32.f32 "
        "{%0,%1,%2,%3}, {%4,%5,%6,%7}, {%8,%9}, {%0,%1,%2,%3};"
        : "+f"(d[0]), "+f"(d[1]), "+f"(d[2]), "+f"(d[3])
        : "r"(a[0]), "r"(a[1]), "r"(a[2]), "r"(a[3]), "r"(b[0]), "r"(b[1]));
}

// packed f32x2 (base ISA on sm_100+ family; SASS FADD2/FFMA2)
#define V8_ADD2(d, a, b) \
    asm("add.rn.f32x2 %0, %1, %2;" : "=l"(d) : "l"(a), "l"(b))
#define V8_FMA2(acc, t, w) \
    asm("fma.rn.f32x2 %0, %1, %2, %0;" : "+l"(acc) : "l"(t), "l"(w))

// packed relu on the ALU pipe (IMAX): valid for all non-NaN floats
__device__ __forceinline__ ull v8_relu2(ull t) {
    unsigned lo, hi;
    asm("mov.b64 {%0,%1}, %2;" : "=r"(lo), "=r"(hi) : "l"(t));
    int l2 = max((int)lo, 0);
    int h2 = max((int)hi, 0);
    ull r;
    asm("mov.b64 %0, {%1,%2};" : "=l"(r) : "r"((unsigned)l2), "r"((unsigned)h2));
    return r;
}

// ---------------------------------------------------------------------------
// TF32 tensor-core GEMM, split-K x2: hZ = tf32(A[:, z*384:(z+1)*384]) @ tf32(W1 slice).T
// CTA 64m x 128n x K384; 12 double-buffered k-tiles of 32, ONE barrier/iter.
// 8 warps (2M x 4N), warp tile 32x32. grid = (12, 10, 2), occupancy 2.
// ---------------------------------------------------------------------------
#define V8_ST     40
#define V8_ASZ    (2 * 64 * V8_ST)
#define V8_BSZ    (2 * 128 * V8_ST)
#define V8_SMEM   ((V8_ASZ + V8_BSZ) * 4)

__global__ void __launch_bounds__(256, 2)
v8_gemm(const float* __restrict__ query,
        const float* __restrict__ support,
        const float* __restrict__ W1,
        const float* __restrict__ b1)
{
    extern __shared__ __align__(16) float smem[];
    float* As = smem;              // [2][64][40]
    float* Bs = smem + V8_ASZ;     // [2][128][40]

    const int tid  = threadIdx.x;
    const int lane = tid & 31;
    const int wid  = tid >> 5;
    const int warpM = wid & 1;
    const int warpN = wid >> 1;
    const int g = lane >> 2;
    const int t = lane & 3;

    const int  z    = blockIdx.z;            // split-K index
    const int  kOff = z * KSPLIT;
    const bool isQ  = (blockIdx.y < 2);
    const float* Arow = isQ ? (query + (size_t)blockIdx.y * 64 * D_IN)
                            : (support + (size_t)(blockIdx.y - 2) * 64 * D_IN);
    const int   wOff  = (isQ ? 0 : D_IN) + kOff;
    const int   jBase = blockIdx.x * 128;
    float* Hq = z ? v8_hq1 : v8_hq0;
    float* Hs = z ? v8_hs1 : v8_hs0;
    float* Crow = isQ ? (Hq + (size_t)blockIdx.y * 64 * TWO_D)
                      : (Hs + (size_t)(blockIdx.y - 2) * 64 * TWO_D);

    const int a_row = tid >> 2, a_ks = tid & 3;
    const int b_row0 = tid >> 2, b_ks0 = tid & 3;
    const int b_row1 = (tid + 256) >> 2, b_ks1 = tid & 3;
    const float* aSeg  = Arow + (size_t)a_row * D_IN + kOff + a_ks * 8;
    const float* bSeg0 = W1 + (size_t)(jBase + b_row0) * TWO_D + wOff + b_ks0 * 8;
    const float* bSeg1 = W1 + (size_t)(jBase + b_row1) * TWO_D + wOff + b_ks1 * 8;

    float4 pa0, pa1, pb00, pb01, pb10, pb11;
    #define V8_PREFETCH(kb) do {                                   \
        pa0  = *(const float4*)(aSeg  + (kb));                     \
        pa1  = *(const float4*)(aSeg  + (kb) + 4);                 \
        pb00 = *(const float4*)(bSeg0 + (kb));                     \
        pb01 = *(const float4*)(bSeg0 + (kb) + 4);                 \
        pb10 = *(const float4*)(bSeg1 + (kb));                     \
        pb11 = *(const float4*)(bSeg1 + (kb) + 4);                 \
    } while (0)

    #define V8_STAGE(buf) do {                                                     \
        float* ap = As + ((buf) * 64 + a_row) * V8_ST + a_ks * 8;                  \
        float2 p;                                                                  \
        p.x = v8_tf32(pa0.x); p.y = v8_tf32(pa1.x); *(float2*)(ap + 0) = p;        \
        p.x = v8_tf32(pa0.y); p.y = v8_tf32(pa1.y); *(float2*)(ap + 2) = p;        \
        p.x = v8_tf32(pa0.z); p.y = v8_tf32(pa1.z); *(float2*)(ap + 4) = p;        \
        p.x = v8_tf32(pa0.w); p.y = v8_tf32(pa1.w); *(float2*)(ap + 6) = p;        \
        float* bp = Bs + ((buf) * 128 + b_row0) * V8_ST + b_ks0 * 8;               \
        p.x = v8_tf32(pb00.x); p.y = v8_tf32(pb01.x); *(float2*)(bp + 0) = p;      \
        p.x = v8_tf32(pb00.y); p.y = v8_tf32(pb01.y); *(float2*)(bp + 2) = p;      \
        p.x = v8_tf32(pb00.z); p.y = v8_tf32(pb01.z); *(float2*)(bp + 4) = p;      \
        p.x = v8_tf32(pb00.w); p.y = v8_tf32(pb01.w); *(float2*)(bp + 6) = p;      \
        bp = Bs + ((buf) * 128 + b_row1) * V8_ST + b_ks1 * 8;                      \
        p.x = v8_tf32(pb10.x); p.y = v8_tf32(pb11.x); *(float2*)(bp + 0) = p;      \
        p.x = v8_tf32(pb10.y); p.y = v8_tf32(pb11.y); *(float2*)(bp + 2) = p;      \
        p.x = v8_tf32(pb10.z); p.y = v8_tf32(pb11.z); *(float2*)(bp + 4) = p;      \
        p.x = v8_tf32(pb10.w); p.y = v8_tf32(pb11.w); *(float2*)(bp + 6) = p;      \
    } while (0)

    float d[2][4][4] = {};

    // prologue: tile0 staged, tile1 in regs
    V8_PREFETCH(0);
    V8_STAGE(0);
    V8_PREFETCH(32);

    for (int kt = 0; kt < 12; kt++) {
        const int buf = kt & 1;
        __syncthreads();                       // buf fully staged by all threads
        if (kt < 11) {
            V8_STAGE(buf ^ 1);                 // overlaps with compute below
            if (kt < 10) V8_PREFETCH((kt + 2) * 32);
        }

        const float* Ab = As + buf * 64 * V8_ST;
        const float* Bb = Bs + buf * 128 * V8_ST;
        #pragma unroll
        for (int s = 0; s < 4; s++) {
            unsigned afr[2][4];
            #pragma unroll
            for (int mf = 0; mf < 2; mf++) {
                const int r0 = warpM * 32 + mf * 16 + g;
                float2 p0 = *(const float2*)(Ab + r0 * V8_ST + s * 8 + t * 2);
                float2 p1 = *(const float2*)(Ab + (r0 + 8) * V8_ST + s * 8 + t * 2);
                afr[mf][0] = __float_as_uint(p0.x);
                afr[mf][1] = __float_as_uint(p1.x);
                afr[mf][2] = __float_as_uint(p0.y);
                afr[mf][3] = __float_as_uint(p1.y);
            }
            #pragma unroll
            for (int nf = 0; nf < 4; nf++) {
                const int n = warpN * 32 + nf * 8 + g;
                float2 q = *(const float2*)(Bb + n * V8_ST + s * 8 + t * 2);
                unsigned bfr[2] = { __float_as_uint(q.x), __float_as_uint(q.y) };
                v8_mma(d[0][nf], afr[0], bfr);
                v8_mma(d[1][nf], afr[1], bfr);
            }
        }
    }

    // epilogue: bias only on query z==0 partial
    const bool addBias = isQ && (z == 0);
    #pragma unroll
    for (int mf = 0; mf < 2; mf++) {
        const int r0 = warpM * 32 + mf * 16 + g;
        #pragma unroll
        for (int nf = 0; nf < 4; nf++) {
            const int c0 = jBase + warpN * 32 + nf * 8 + t * 2;
            float2 bias = make_float2(0.f, 0.f);
            if (addBias) bias = *(const float2*)(b1 + c0);
            float2 v0 = make_float2(d[mf][nf][0] + bias.x, d[mf][nf][1] + bias.y);
            float2 v1 = make_float2(d[mf][nf][2] + bias.x, d[mf][nf][3] + bias.y);
            *(float2*)(Crow + (size_t)r0 * TWO_D + c0)       = v0;
            *(float2*)(Crow + (size_t)(r0 + 8) * TWO_D + c0) = v1;
        }
    }
}

// ---------------------------------------------------------------------------
// Scores partial, packed f32x2 + ALU-pipe relu. Split-K partials summed
// during SMEM staging (deterministic fixed order).
// grid = (8, 4, JCHUNKS=8), 256 threads.
// ---------------------------------------------------------------------------
__global__ void v8_scores(const float* __restrict__ W2)
{
    __shared__ __align__(16) float2 Aq2[8][34];
    __shared__ __align__(16) float2 Bs2[8][66];
    __shared__ float2 ws2[8];

    const int tid    = threadIdx.x;
    const int sBase  = blockIdx.x * 64;
    const int qBase  = blockIdx.y * 32;
    const int jcBase = blockIdx.z * JPER;
    const int ty = tid >> 4;
    const int tx = tid & 15;

    const int aq_q  = tid >> 3;
    const int aq_jp = tid & 7;
    const size_t hqOff = (size_t)(qBase + aq_q) * TWO_D + jcBase + aq_jp * 2;
    const int bs_s  = tid >> 2;
    const int bs_jp = (tid & 3) * 2;
    const size_t hsOff = (size_t)(sBase + bs_s) * TWO_D + jcBase + bs_jp * 2;

    double dacc[2][4] = {};
    ull acc2[2][4] = {};

    for (int jt = 0; jt < JPER; jt += 16) {
        float2 a0 = *(const float2*)(v8_hq0 + hqOff + jt);
        float2 a1 = *(const float2*)(v8_hq1 + hqOff + jt);
        float4 b0 = *(const float4*)(v8_hs0 + hsOff + jt);
        float4 b1v = *(const float4*)(v8_hs1 + hsOff + jt);
        float2 aval = make_float2(a0.x + a1.x, a0.y + a1.y);
        float4 bval = make_float4(b0.x + b1v.x, b0.y + b1v.y,
                                  b0.z + b1v.z, b0.w + b1v.w);
        float2 wval = make_float2(0.f, 0.f);
        if (tid < 8) wval = *(const float2*)(W2 + jcBase + jt + tid * 2);
        __syncthreads();
        Aq2[aq_jp][aq_q] = aval;
        Bs2[bs_jp][bs_s]     = make_float2(bval.x, bval.y);
        Bs2[bs_jp + 1][bs_s] = make_float2(bval.z, bval.w);
        if (tid < 8) ws2[tid] = wval;
        __syncthreads();

        #pragma unroll
        for (int jp = 0; jp < 8; jp++) {
            const ull w2v = *(const ull*)&ws2[jp];
            const ull a0u = *(const ull*)&Aq2[jp][ty * 2];
            const ull a1u = *(const ull*)&Aq2[jp][ty * 2 + 1];
            #pragma unroll
            for (int l = 0; l < 4; l++) {
                const ull bv = *(const ull*)&Bs2[jp][tx + l * 16];
                ull t0; V8_ADD2(t0, a0u, bv);
                t0 = v8_relu2(t0);
                V8_FMA2(acc2[0][l], t0, w2v);
                ull t1; V8_ADD2(t1, a1u, bv);
                t1 = v8_relu2(t1);
                V8_FMA2(acc2[1][l], t1, w2v);
            }
        }

        if ((jt & 63) == 48) {
            #pragma unroll
            for (int i = 0; i < 2; i++)
                #pragma unroll
                for (int l = 0; l < 4; l++) {
                    unsigned lo, hi;
                    asm("mov.b64 {%0,%1}, %2;" : "=r"(lo), "=r"(hi) : "l"(acc2[i][l]));
                    dacc[i][l] += (double)(__uint_as_float(lo) + __uint_as_float(hi));
                    acc2[i][l] = 0ull;
                }
        }
    }

    double* outp = v8_part + (size_t)blockIdx.z * (Q_N * S_N);
    #pragma unroll
    for (int i = 0; i < 2; i++)
        #pragma unroll
        for (int l = 0; l < 4; l++)
            outp[(size_t)(qBase + ty * 2 + i) * S_N + sBase + tx + l * 16] = dacc[i][l];
}

// ---------------------------------------------------------------------------
// Per-query aggregate + softmax + pred + merged final loss reduction (ticket).
// grid = 128 blocks, 128 threads. All fp64, deterministic.
// ---------------------------------------------------------------------------
__global__ void v8_agg(const int* __restrict__ labels,
                       const int* __restrict__ targets,
                       const float* __restrict__ b2,
                       float* __restrict__ out, int out_size)
{
    __shared__ double sc[S_N];
    __shared__ int    lab[S_N];
    __shared__ double aggv[C_N];
    __shared__ double redv[C_N];
    __shared__ int    redi[C_N];
    __shared__ double rede[C_N];
    __shared__ int    isLast;
    __shared__ double lred[Q_N];

    const int q   = blockIdx.x;
    const int tid = threadIdx.x;
    const double b2v = (double)b2[0];

    for (int s = tid; s < S_N; s += 128) lab[s] = labels[s];

    for (int s = tid; s < S_N; s += 128) {
        double v = 0.0;
        #pragma unroll
        for (int z = 0; z < JCHUNKS; z++)
            v += v8_part[(size_t)z * (Q_N * S_N) + (size_t)q * S_N + s];
        sc[s] = v + b2v;
    }
    __syncthreads();

    if (tid < C_N) {
        double ssum = 0.0;
        int cnt = 0;
        for (int s = 0; s < S_N; s++)
            if (lab[s] == tid) { ssum += sc[s]; cnt++; }
        aggv[tid] = ssum / (double)(cnt > 1 ? cnt : 1);
        redv[tid] = aggv[tid];
        redi[tid] = tid;
    }
    __syncthreads();

    #pragma unroll
    for (int off = C_N / 2; off > 0; off >>= 1) {
        if (tid < off) {
            if (redv[tid + off] > redv[tid] ||
                (redv[tid + off] == redv[tid] && redi[tid + off] < redi[tid])) {
                redv[tid] = redv[tid + off];
                redi[tid] = redi[tid + off];
            }
        }
        __syncthreads();
    }
    const double mx = redv[0];
    const int    am = redi[0];

    if (tid < C_N) rede[tid] = exp(aggv[tid] - mx);
    __syncthreads();
    #pragma unroll
    for (int off = C_N / 2; off > 0; off >>= 1) {
        if (tid < off) rede[tid] += rede[tid + off];
        __syncthreads();
    }

    if (tid == 0) {
        const int tgt = targets[q];
        const double logp = aggv[tgt] - mx - log(rede[0]);
        v8_loss[q] = -logp;
        if (1 + q < out_size) out[1 + q] = (am == tgt) ? 1.0f : 0.0f;
        __threadfence();
        unsigned tk = atomicAdd(&v8_ticket, 1u);
        isLast = (tk == (unsigned)(Q_N - 1));
    }
    __syncthreads();

    if (isLast) {
        __threadfence();
        lred[tid] = v8_loss[tid];
        __syncthreads();
        #pragma unroll
        for (int off = Q_N / 2; off > 0; off >>= 1) {
            if (tid < off) lred[tid] += lred[tid + off];
            __syncthreads();
        }
        if (tid == 0) {
            if (out_size > 0) out[0] = (float)(lred[0] / (double)Q_N);
            v8_ticket = 0;
        }
    }
}

// ---------------------------------------------------------------------------
extern "C" void kernel_launch(void* const* d_in, const int* in_sizes, int n_in,
                              void* d_out, int out_size)
{
    const float* query   = (const float*)d_in[0];
    const float* support = (const float*)d_in[1];
    const float* W1      = (const float*)d_in[2];
    const float* b1      = (const float*)d_in[3];
    const float* W2      = (const float*)d_in[4];
    const float* b2      = (const float*)d_in[5];
    const int*   labels  = (const int*)  d_in[6];
    const int*   targets = (const int*)  d_in[7];
    (void)in_sizes; (void)n_in;

    float* out = (float*)d_out;

    cudaFuncSetAttribute(v8_gemm, cudaFuncAttributeMaxDynamicSharedMemorySize, V8_SMEM);

    v8_gemm  <<<dim3(TWO_D/128, 10, 2), 256, V8_SMEM>>>(query, support, W1, b1);
    v8_scores<<<dim3(S_N/64, Q_N/32, JCHUNKS), 256>>>(W2);
    v8_agg   <<<Q_N, 128>>>(labels, targets, b2, out, out_size);
}